// round 2
// baseline (speedup 1.0000x reference)
#include <cuda_runtime.h>

#define B_   16
#define IC_  128
#define OC_  128
#define SD_  512
#define H_   128
#define W_   128
#define HW_  (H_*W_)

// conv_scale = 1/sqrt(IC*K*K) = 1/sqrt(1152); lin_scale = 1/sqrt(512)
#define CONV_SCALE 0.029462782549439476f
#define LIN_SCALE  0.044194173824159216f

// Scratch (device globals — no allocation allowed in kernel_launch)
__device__ float g_s[B_ * IC_];                 // modulation s[b][ic]
__device__ float g_w[B_ * IC_ * 9 * OC_];       // modulated+demodulated weights, layout [b][ic][k][oc]

// ---------------------------------------------------------------------------
// Kernel 1: s[b][ic] = dot(style[b], mod_w[ic]) * lin_scale + mod_b[ic]
// One warp per output. grid 512 x 128 threads = 2048 warps-outputs.
// ---------------------------------------------------------------------------
__global__ void mod_kernel(const float* __restrict__ style,
                           const float* __restrict__ mod_w,
                           const float* __restrict__ mod_b) {
    int warp = threadIdx.x >> 5;
    int lane = threadIdx.x & 31;
    int idx  = blockIdx.x * 4 + warp;          // 0..2047
    int b  = idx >> 7;
    int ic = idx & 127;
    const float* st = style + b * SD_;
    const float* mw = mod_w + ic * SD_;
    float sum = 0.f;
    #pragma unroll 4
    for (int j = lane; j < SD_; j += 32) sum += st[j] * mw[j];
    #pragma unroll
    for (int o = 16; o; o >>= 1) sum += __shfl_xor_sync(0xffffffffu, sum, o);
    if (lane == 0) g_s[idx] = sum * LIN_SCALE + mod_b[ic];
}

// ---------------------------------------------------------------------------
// Kernel 2: per (b, oc): v = conv_scale * weight * s; demod = rsqrt(sum v^2);
// write g_w[b][ic][k][oc] = v * demod   (oc-innermost for packed conv loads)
// grid (OC_, B_), 128 threads (thread = ic)
// ---------------------------------------------------------------------------
__global__ void demod_kernel(const float* __restrict__ weight) {
    int oc = blockIdx.x;
    int b  = blockIdx.y;
    int ic = threadIdx.x;

    float s = g_s[b * IC_ + ic];
    const float* wp = weight + ((size_t)oc * IC_ + ic) * 9;

    float v[9];
    float ss = 0.f;
    #pragma unroll
    for (int k = 0; k < 9; ++k) {
        v[k] = CONV_SCALE * wp[k] * s;
        ss += v[k] * v[k];
    }
    // block reduce over 128 threads
    #pragma unroll
    for (int o = 16; o; o >>= 1) ss += __shfl_xor_sync(0xffffffffu, ss, o);
    __shared__ float red[4];
    if ((threadIdx.x & 31) == 0) red[threadIdx.x >> 5] = ss;
    __syncthreads();
    float tot = red[0] + red[1] + red[2] + red[3];
    float demod = rsqrtf(tot + 1e-8f);

    float* out = g_w + ((size_t)(b * IC_ + ic) * 9) * OC_ + oc;
    #pragma unroll
    for (int k = 0; k < 9; ++k) out[k * OC_] = v[k] * demod;
}

// ---------------------------------------------------------------------------
// Kernel 3: direct 3x3 conv.
// Block: 64-OC slice x 16x16 spatial tile of one sample. 128 threads.
// Thread: pixel column tx (0..15), row pair 2*ty, 2*ty+1 (ty 0..7).
// Accumulators: 32 oc-pairs x 2 pixels as packed f32x2 (fma.rn.f32x2).
// IC streamed in chunks of 8 through SMEM (content halo tile + weights).
// Per ic: 12 broadcast LDS (taps) + 288 broadcast LDS.64 (weights)
//         vs 576 packed FMAs -> FMA-pipe bound by ~2x.
// ---------------------------------------------------------------------------
#define ICCH 8

__global__ void __launch_bounds__(128) conv_kernel(const float* __restrict__ content,
                                                   float* __restrict__ out) {
    __shared__ float              sC[ICCH][18][18];
    __shared__ unsigned long long sW[ICCH][9][32];   // oc pairs, 8B aligned

    const int bx = blockIdx.x;                // W tile
    const int by = blockIdx.y;                // H tile
    const int b  = blockIdx.z >> 1;
    const int ocBase = (blockIdx.z & 1) * 64;

    const int tid = threadIdx.x;
    const int tx = tid & 15;
    const int ty = tid >> 4;                  // 0..7
    const int r0 = ty * 2;

    unsigned long long acc0[32], acc1[32];
    #pragma unroll
    for (int p = 0; p < 32; ++p) { acc0[p] = 0ull; acc1[p] = 0ull; }

    const float* cbase = content + (size_t)b * IC_ * HW_;
    const int gy0 = by * 16 - 1;
    const int gx0 = bx * 16 - 1;

    #pragma unroll 1
    for (int icb = 0; icb < IC_; icb += ICCH) {
        // ---- load content halo tile (zero-padded) ----
        #pragma unroll 1
        for (int i = tid; i < ICCH * 324; i += 128) {
            int icl = i / 324;
            int rem = i - icl * 324;
            int r = rem / 18;
            int c = rem - r * 18;
            int gy = gy0 + r, gx = gx0 + c;
            float v = 0.f;
            if ((unsigned)gy < (unsigned)H_ && (unsigned)gx < (unsigned)W_)
                v = cbase[(size_t)(icb + icl) * HW_ + gy * W_ + gx];
            sC[icl][r][c] = v;
        }
        // ---- load weights [icl][k][oc 0..63] (coalesced from g_w) ----
        {
            const float* wbase = g_w + ((size_t)(b * IC_ + icb) * 9) * OC_ + ocBase;
            float* sWf = (float*)&sW[0][0][0];
            #pragma unroll 1
            for (int i = tid; i < ICCH * 9 * 64; i += 128) {
                int icl = i / 576;
                int rem = i - icl * 576;
                int k  = rem >> 6;
                int oc = rem & 63;
                sWf[(icl * 9 + k) * 64 + oc] = wbase[(icl * 9 + k) * OC_ + oc];
            }
        }
        __syncthreads();

        #pragma unroll 1
        for (int ic = 0; ic < ICCH; ++ic) {
            // content taps: 4 rows x 3 cols, broadcast-packed to f32x2
            unsigned long long c2[4][3];
            #pragma unroll
            for (int i = 0; i < 4; ++i)
                #pragma unroll
                for (int j = 0; j < 3; ++j) {
                    float v = sC[ic][r0 + i][tx + j];
                    asm("mov.b64 %0, {%1,%1};" : "=l"(c2[i][j]) : "f"(v));
                }
            #pragma unroll
            for (int p = 0; p < 32; ++p) {
                unsigned long long w2[9];
                #pragma unroll
                for (int k = 0; k < 9; ++k) w2[k] = sW[ic][k][p];
                #pragma unroll
                for (int dy = 0; dy < 3; ++dy) {
                    #pragma unroll
                    for (int dx = 0; dx < 3; ++dx) {
                        asm("fma.rn.f32x2 %0, %1, %2, %0;"
                            : "+l"(acc0[p]) : "l"(w2[dy * 3 + dx]), "l"(c2[dy][dx]));
                        asm("fma.rn.f32x2 %0, %1, %2, %0;"
                            : "+l"(acc1[p]) : "l"(w2[dy * 3 + dx]), "l"(c2[dy + 1][dx]));
                    }
                }
            }
        }
        __syncthreads();
    }

    // ---- epilogue ----
    const int y0 = by * 16 + r0;
    const int x  = bx * 16 + tx;
    float* obase = out + ((size_t)b * OC_ + ocBase) * HW_ + x;
    #pragma unroll
    for (int p = 0; p < 32; ++p) {
        float a0, a1, b0v, b1v;
        asm("mov.b64 {%0,%1}, %2;" : "=f"(a0), "=f"(a1) : "l"(acc0[p]));
        asm("mov.b64 {%0,%1}, %2;" : "=f"(b0v), "=f"(b1v) : "l"(acc1[p]));
        size_t o0 = (size_t)(2 * p) * HW_;
        size_t o1 = (size_t)(2 * p + 1) * HW_;
        obase[o0 + (size_t)y0 * W_]       = a0;
        obase[o1 + (size_t)y0 * W_]       = a1;
        obase[o0 + (size_t)(y0 + 1) * W_] = b0v;
        obase[o1 + (size_t)(y0 + 1) * W_] = b1v;
    }
}

// ---------------------------------------------------------------------------
extern "C" void kernel_launch(void* const* d_in, const int* in_sizes, int n_in,
                              void* d_out, int out_size) {
    const float* content = (const float*)d_in[0];   // [16,128,128,128]
    const float* style   = (const float*)d_in[1];   // [16,512]
    const float* weight  = (const float*)d_in[2];   // [1,128,128,3,3]
    const float* mod_w   = (const float*)d_in[3];   // [128,512]
    const float* mod_b   = (const float*)d_in[4];   // [128]
    float* out = (float*)d_out;                     // [16,128,128,128]

    mod_kernel<<<512, 128>>>(style, mod_w, mod_b);
    demod_kernel<<<dim3(OC_, B_), 128>>>(weight);
    conv_kernel<<<dim3(W_ / 16, H_ / 16, B_ * 2), 128>>>(content, out);
}

// round 7
// speedup vs baseline: 12.2749x; 12.2749x over previous
#include <cuda_runtime.h>
#include <cuda_fp16.h>
#include <cstdint>

#define B_   16
#define IC_  128
#define OC_  128
#define SD_  512
#define H_   128
#define W_   128
#define HW_  (H_*W_)   // 16384

#define CONV_SCALE 0.029462782549439476f   // 1/sqrt(1152)
#define LIN_SCALE  0.044194173824159216f   // 1/sqrt(512)

// ---------------- device scratch (no allocation allowed) -------------------
__device__ float  g_s[B_ * IC_];                          // modulation s[b][ic]
__device__ __half g_wh[(size_t)B_ * 9 * OC_ * IC_];       // [b][tap][oc][ic] fp16
__device__ __half g_ch[(size_t)B_ * HW_ * IC_];           // [b][pixel][ic] fp16 channels-last

// ---------------- helpers ---------------------------------------------------
__device__ __forceinline__ uint32_t s2u(const void* p) {
    uint32_t a;
    asm("{ .reg .u64 t; cvta.to.shared.u64 t, %1; cvt.u32.u64 %0, t; }" : "=r"(a) : "l"(p));
    return a;
}
__device__ __forceinline__ void cpa16(uint32_t dst, const void* src, int sz) {
    asm volatile("cp.async.cg.shared.global [%0], [%1], 16, %2;"
                 :: "r"(dst), "l"(src), "r"(sz) : "memory");
}
__device__ __forceinline__ void ldsm_x4(uint32_t a, uint32_t& r0, uint32_t& r1,
                                        uint32_t& r2, uint32_t& r3) {
    asm volatile("ldmatrix.sync.aligned.m8n8.x4.shared.b16 {%0,%1,%2,%3}, [%4];"
                 : "=r"(r0), "=r"(r1), "=r"(r2), "=r"(r3) : "r"(a));
}
__device__ __forceinline__ void hmma(float& c0, float& c1, float& c2, float& c3,
                                     uint32_t a0, uint32_t a1, uint32_t a2, uint32_t a3,
                                     uint32_t b0, uint32_t b1) {
    asm volatile(
        "mma.sync.aligned.m16n8k16.row.col.f32.f16.f16.f32 "
        "{%0,%1,%2,%3}, {%4,%5,%6,%7}, {%8,%9}, {%0,%1,%2,%3};"
        : "+f"(c0), "+f"(c1), "+f"(c2), "+f"(c3)
        : "r"(a0), "r"(a1), "r"(a2), "r"(a3), "r"(b0), "r"(b1));
}

// ---------------------------------------------------------------------------
// Kernel 1: s[b][ic] = dot(style[b], mod_w[ic]) * lin_scale + mod_b[ic]
// ---------------------------------------------------------------------------
__global__ void mod_kernel(const float* __restrict__ style,
                           const float* __restrict__ mod_w,
                           const float* __restrict__ mod_b) {
    int warp = threadIdx.x >> 5, lane = threadIdx.x & 31;
    int idx  = blockIdx.x * 4 + warp;
    int b = idx >> 7, ic = idx & 127;
    const float* st = style + b * SD_;
    const float* mw = mod_w + ic * SD_;
    float sum = 0.f;
    #pragma unroll 4
    for (int j = lane; j < SD_; j += 32) sum += st[j] * mw[j];
    #pragma unroll
    for (int o = 16; o; o >>= 1) sum += __shfl_xor_sync(0xffffffffu, sum, o);
    if (lane == 0) g_s[idx] = sum * LIN_SCALE + mod_b[ic];
}

// ---------------------------------------------------------------------------
// Kernel 2: demodulate, write fp16 weights g_wh[b][tap][oc][ic]
// ---------------------------------------------------------------------------
__global__ void demod_kernel(const float* __restrict__ weight) {
    int oc = blockIdx.x, b = blockIdx.y, ic = threadIdx.x;
    float s = g_s[b * IC_ + ic];
    const float* wp = weight + ((size_t)oc * IC_ + ic) * 9;
    float v[9], ss = 0.f;
    #pragma unroll
    for (int k = 0; k < 9; ++k) { v[k] = CONV_SCALE * wp[k] * s; ss += v[k] * v[k]; }
    #pragma unroll
    for (int o = 16; o; o >>= 1) ss += __shfl_xor_sync(0xffffffffu, ss, o);
    __shared__ float red[4];
    if ((threadIdx.x & 31) == 0) red[threadIdx.x >> 5] = ss;
    __syncthreads();
    float demod = rsqrtf(red[0] + red[1] + red[2] + red[3] + 1e-8f);
    #pragma unroll
    for (int k = 0; k < 9; ++k)
        g_wh[((size_t)(b * 9 + k) * OC_ + oc) * IC_ + ic] = __float2half(v[k] * demod);
}

// ---------------------------------------------------------------------------
// Kernel 3: content -> fp16 channels-last: g_ch[b][y*W+x][ic] = content[b][ic][y][x]
// block = (y, b), 256 threads; smem transpose (row pad kills bank conflicts)
// ---------------------------------------------------------------------------
__global__ void prep_content(const float* __restrict__ content) {
    __shared__ __half sm[128][129];
    int y = blockIdx.x, b = blockIdx.y, tid = threadIdx.x;
    const float* src = content + (size_t)b * IC_ * HW_ + y * W_;
    for (int i = tid; i < IC_ * W_; i += 256) {
        int ic = i >> 7, x = i & 127;
        sm[x][ic] = __float2half(src[(size_t)ic * HW_ + x]);
    }
    __syncthreads();
    __half* dst = g_ch + ((size_t)b * HW_ + (size_t)y * W_) * IC_;
    for (int i = tid; i < IC_ * W_; i += 256) {
        int x = i >> 7, ic = i & 127;
        dst[(size_t)x * IC_ + ic] = sm[x][ic];
    }
}

// ---------------------------------------------------------------------------
// Kernel 4: implicit GEMM conv via ldmatrix + mma.sync (HMMA, sm_100-safe).
// CTA = (row y, sample b): D[128 oc][128 px], K = 9 taps x 128 ic.
// 8 warps: warp_m = wid&3 (32 oc), warp_n = wid>>2 (64 px).
// 18 stages (tap, ic-chunk of 64): A[128 oc][64 ic], B[128 px][64 ic] in SMEM,
// XOR-swizzled 128B rows, cp.async double-buffered.
// x-shift dx = (dx-1)*IC element offset in channels-last row; x edges zero-masked.
// ---------------------------------------------------------------------------
#define NST 18
#define STAGE_BYTES 16384
#define SM_TOTAL (4 * STAGE_BYTES)   // A0 B0 A1 B1

__global__ void __launch_bounds__(256) conv_mma(float* __restrict__ out) {
    extern __shared__ char smem[];
    const uint32_t sb = s2u(smem);
    const int tid = threadIdx.x, wid = tid >> 5, lane = tid & 31;
    const int y = blockIdx.x, b = blockIdx.y;
    const int warp_m = wid & 3, warp_n = wid >> 2;

    const uint32_t Ab[2] = { sb,               sb + 2 * STAGE_BYTES };
    const uint32_t Bb[2] = { sb + STAGE_BYTES, sb + 3 * STAGE_BYTES };

    float acc[2][8][4];
    #pragma unroll
    for (int mt = 0; mt < 2; ++mt)
        #pragma unroll
        for (int nt = 0; nt < 8; ++nt)
            #pragma unroll
            for (int c = 0; c < 4; ++c) acc[mt][nt][c] = 0.f;

    // ---- stage loader (cp.async; 4 x 16B per thread per tile) ----
    auto issue = [&](int s, int p) {
        const int tap = s % 9, chunk = s / 9;
        const int dy = tap / 3 - 1, dx = tap % 3;
        // A: weights, row=oc (128B = 64 halves)
        const char* asrc = (const char*)g_wh
            + ((size_t)(b * 9 + tap) * OC_ * IC_ + chunk * 64) * 2;
        #pragma unroll
        for (int j = 0; j < 4; ++j) {
            int i = tid + j * 256;               // 0..1023
            int row = i >> 3, c16 = i & 7;
            uint32_t off = (uint32_t)(row * 128 + c16 * 16);
            cpa16(Ab[p] + (off ^ (((uint32_t)row & 7u) << 4)),
                  asrc + (size_t)row * IC_ * 2 + c16 * 16, 16);
        }
        // B: content row y+dy (channels-last), x-shift = (dx-1)*IC halves
        const int yy = y + dy;
        const int rowok = (yy >= 0 && yy < H_);
        const int yc = rowok ? yy : 0;
        const __half* brow = g_ch + ((size_t)b * HW_ + (size_t)yc * W_) * IC_;
        #pragma unroll
        for (int j = 0; j < 4; ++j) {
            int i = tid + j * 256;
            int row = i >> 3, c16 = i & 7;       // row = x coordinate
            int xs = row + dx - 1;
            int ok = (rowok && xs >= 0 && xs < W_) ? 16 : 0;
            int xc = (xs >= 0 && xs < W_) ? xs : 0;
            uint32_t off = (uint32_t)(row * 128 + c16 * 16);
            cpa16(Bb[p] + (off ^ (((uint32_t)row & 7u) << 4)),
                  (const char*)(brow + (size_t)xc * IC_ + chunk * 64) + c16 * 16, ok);
        }
        asm volatile("cp.async.commit_group;" ::: "memory");
    };

    issue(0, 0);

    #pragma unroll 1
    for (int s = 0; s < NST; ++s) {
        const int p = s & 1;
        if (s + 1 < NST) issue(s + 1, (s + 1) & 1);
        if (s + 1 < NST) asm volatile("cp.async.wait_group 1;" ::: "memory");
        else             asm volatile("cp.async.wait_group 0;" ::: "memory");
        __syncthreads();

        #pragma unroll
        for (int kst = 0; kst < 4; ++kst) {
            uint32_t a[2][4];
            #pragma unroll
            for (int mt = 0; mt < 2; ++mt) {
                int row = warp_m * 32 + mt * 16 + (lane & 15);
                int kc  = kst * 2 + (lane >> 4);
                uint32_t off = (uint32_t)(row * 128 + kc * 16);
                uint32_t ad = Ab[p] + (off ^ (((uint32_t)row & 7u) << 4));
                ldsm_x4(ad, a[mt][0], a[mt][1], a[mt][2], a[mt][3]);
            }
            uint32_t bf[8][2];
            #pragma unroll
            for (int ntp = 0; ntp < 4; ++ntp) {
                int n  = warp_n * 64 + ntp * 16 + ((lane >> 4) << 3) + (lane & 7);
                int kc = kst * 2 + ((lane >> 3) & 1);
                uint32_t off = (uint32_t)(n * 128 + kc * 16);
                uint32_t ad = Bb[p] + (off ^ (((uint32_t)n & 7u) << 4));
                ldsm_x4(ad, bf[2 * ntp][0], bf[2 * ntp][1],
                            bf[2 * ntp + 1][0], bf[2 * ntp + 1][1]);
            }
            #pragma unroll
            for (int mt = 0; mt < 2; ++mt)
                #pragma unroll
                for (int nt = 0; nt < 8; ++nt)
                    hmma(acc[mt][nt][0], acc[mt][nt][1], acc[mt][nt][2], acc[mt][nt][3],
                         a[mt][0], a[mt][1], a[mt][2], a[mt][3],
                         bf[nt][0], bf[nt][1]);
        }
        __syncthreads();
    }

    // ---- epilogue: c0,c1 -> (m = t/4, n = (t%4)*2), c2,c3 -> m+8 ----
    const int qm = lane >> 2, qn = (lane & 3) * 2;
    #pragma unroll
    for (int mt = 0; mt < 2; ++mt) {
        #pragma unroll
        for (int nt = 0; nt < 8; ++nt) {
            int oc0 = warp_m * 32 + mt * 16 + qm;
            int px  = warp_n * 64 + nt * 8 + qn;
            float* d0 = out + ((size_t)(b * OC_ + oc0)) * HW_ + (size_t)y * W_ + px;
            *reinterpret_cast<float2*>(d0) =
                make_float2(acc[mt][nt][0], acc[mt][nt][1]);
            *reinterpret_cast<float2*>(d0 + 8 * HW_) =
                make_float2(acc[mt][nt][2], acc[mt][nt][3]);
        }
    }
}

// ---------------------------------------------------------------------------
extern "C" void kernel_launch(void* const* d_in, const int* in_sizes, int n_in,
                              void* d_out, int out_size) {
    const float* content = (const float*)d_in[0];
    const float* style   = (const float*)d_in[1];
    const float* weight  = (const float*)d_in[2];
    const float* mod_w   = (const float*)d_in[3];
    const float* mod_b   = (const float*)d_in[4];
    float* out = (float*)d_out;

    cudaFuncSetAttribute(conv_mma, cudaFuncAttributeMaxDynamicSharedMemorySize, SM_TOTAL);

    mod_kernel<<<512, 128>>>(style, mod_w, mod_b);
    demod_kernel<<<dim3(OC_, B_), 128>>>(weight);
    prep_content<<<dim3(H_, B_), 256>>>(content);
    conv_mma<<<dim3(H_, B_), 256, SM_TOTAL>>>(out);
}